// round 8
// baseline (speedup 1.0000x reference)
#include <cuda_runtime.h>
#include <cuda_bf16.h>

// Problem shape (fixed by reference setup_inputs)
#define B_DIM 32
#define C_DIM 512
#define HW    4096            // 64*64
#define KTOP  256             // 0.5 * C
#define NBC   (B_DIM * C_DIM) // 16384

// Grid: 16384 streaming blocks + 32 per-batch selector blocks + 1 final block
#define GRID_TOTAL (NBC + B_DIM + 1)

// Scratch (no cudaMalloc allowed; zero-initialized at module load)
__device__ float g_ssq[NBC];            // per-(b,c) sum of targets^2 (ranking key)
__device__ float g_ssd[NBC];            // per-(b,c) sum of (in - tgt)^2
__device__ float g_batch[B_DIM];        // per-batch kept-ssd sums
__device__ unsigned int g_bdone[B_DIM]; // per-batch completion counters (self-reset)
__device__ unsigned int g_done2;        // selector completion counter (self-reset)

// Fire-and-forget release reduction: orders this thread's prior global stores
// before the increment; NO return value -> no warp stall, CTA retires
// immediately (the R4/R6 mistake was the value-returning ATOMG at block exit).
__device__ __forceinline__ void red_add_release(unsigned int* p, unsigned int v)
{
    asm volatile("red.release.gpu.global.add.u32 [%0], %1;"
                 :: "l"(p), "r"(v) : "memory");
}

__device__ __forceinline__ unsigned int ld_acquire(const unsigned int* p)
{
    unsigned int v;
    asm volatile("ld.acquire.gpu.global.u32 %0, [%1];" : "=r"(v) : "l"(p) : "memory");
    return v;
}

// ---------------------------------------------------------------------------
// Single kernel, three block roles by blockIdx.x:
//   [0, NBC):          streaming reduce of one (b,c) plane (identical load
//                      path to the 79.5us/85.7%-DRAM kernel; exit cost is one
//                      non-blocking REDG).
//   [NBC, NBC+32):     per-batch selector. Spins (acquire + nanosleep) until
//                      its batch's 512 planes are published, then rank-count
//                      top-k from L2 (__ldcg), fixed-order reduce -> g_batch,
//                      REDG g_done2. Scheduled in the last waves; 31/32 hide
//                      under the streaming tail.
//   NBC+32:            final. Spins on g_done2==32, fixed-order 32-sum ->
//                      scalar, resets g_done2.
// All counters self-reset; all reductions fixed-order -> deterministic.
// No deadlock: <=33 of 1184 CTA slots spin, the rest drain streaming blocks.
// ---------------------------------------------------------------------------
__global__ __launch_bounds__(256, 8) void fused_kernel(
    const float* __restrict__ inp,
    const float* __restrict__ tgt,
    float* __restrict__ out)
{
    const int bid = blockIdx.x;
    const int t = threadIdx.x;
    const int warp = t >> 5;
    const int lane = t & 31;

    if (bid < NBC) {
        // ------------- Role 1: streaming reduce (HBM-bound) ----------------
        const float4* __restrict__ ip =
            reinterpret_cast<const float4*>(inp + (size_t)bid * HW);
        const float4* __restrict__ tp =
            reinterpret_cast<const float4*>(tgt + (size_t)bid * HW);

        float ssq = 0.0f;
        float ssd = 0.0f;

#pragma unroll
        for (int i = 0; i < 4; i++) {
            float4 a = __ldcs(ip + t + i * 256);
            float4 b = __ldcs(tp + t + i * 256);
            ssq = fmaf(b.x, b.x, ssq);
            ssq = fmaf(b.y, b.y, ssq);
            ssq = fmaf(b.z, b.z, ssq);
            ssq = fmaf(b.w, b.w, ssq);
            float dx = a.x - b.x;
            float dy = a.y - b.y;
            float dz = a.z - b.z;
            float dw = a.w - b.w;
            ssd = fmaf(dx, dx, ssd);
            ssd = fmaf(dy, dy, ssd);
            ssd = fmaf(dz, dz, ssd);
            ssd = fmaf(dw, dw, ssd);
        }

#pragma unroll
        for (int off = 16; off > 0; off >>= 1) {
            ssq += __shfl_xor_sync(0xFFFFFFFFu, ssq, off);
            ssd += __shfl_xor_sync(0xFFFFFFFFu, ssd, off);
        }

        __shared__ float s_ssq[8];
        __shared__ float s_ssd[8];
        if (lane == 0) {
            s_ssq[warp] = ssq;
            s_ssd[warp] = ssd;
        }
        __syncthreads();

        if (warp == 0) {
            float q = (lane < 8) ? s_ssq[lane] : 0.0f;
            float d = (lane < 8) ? s_ssd[lane] : 0.0f;
#pragma unroll
            for (int off = 4; off > 0; off >>= 1) {
                q += __shfl_xor_sync(0xFFFFFFFFu, q, off);
                d += __shfl_xor_sync(0xFFFFFFFFu, d, off);
            }
            if (lane == 0) {
                g_ssq[bid] = q;
                g_ssd[bid] = d;
                // non-blocking: release prior stores, no return value
                red_add_release(&g_bdone[bid >> 9], 1u);
            }
        }
        return;   // CTA retires immediately; slot recycles
    }

    if (bid < NBC + B_DIM) {
        // ------------- Role 2: per-batch top-k selector ---------------------
        const int b = bid - NBC;

        __shared__ bool s_ready;
        if (t == 0) {
            // spin until all 512 planes of batch b are published
            while (ld_acquire(&g_bdone[b]) < C_DIM)
                __nanosleep(128);
            s_ready = true;
        }
        __syncthreads();
        (void)s_ready;

        __shared__ float4 s_norm4[C_DIM / 4];   // 512 norms as 128 float4
        if (t < C_DIM / 4)
            s_norm4[t] = __ldcg(reinterpret_cast<const float4*>(g_ssq + b * C_DIM) + t);
        // hoist ssd loads; latency hides under the rank loop
        const int c0 = t;
        const int c1 = t + 256;
        const float ssd0 = __ldcg(g_ssd + b * C_DIM + c0);
        const float ssd1 = __ldcg(g_ssd + b * C_DIM + c1);
        __syncthreads();

        const float* s_norm = reinterpret_cast<const float*>(s_norm4);
        const float v0 = s_norm[c0];
        const float v1 = s_norm[c1];

        int cnt0 = 0, cnt1 = 0;
#pragma unroll 4
        for (int j = 0; j < C_DIM / 4; j++) {
            float4 n = s_norm4[j];             // broadcast, conflict-free
            cnt0 += (n.x > v0) + (n.y > v0) + (n.z > v0) + (n.w > v0);
            cnt1 += (n.x > v1) + (n.y > v1) + (n.z > v1) + (n.w > v1);
        }

        float contrib = 0.0f;
        if (cnt0 < KTOP) contrib += ssd0;
        if (cnt1 < KTOP) contrib += ssd1;

#pragma unroll
        for (int off = 16; off > 0; off >>= 1)
            contrib += __shfl_xor_sync(0xFFFFFFFFu, contrib, off);

        __shared__ float s_p[8];
        if (lane == 0) s_p[warp] = contrib;
        __syncthreads();

        if (t == 0) {
            float x = ((s_p[0] + s_p[1]) + (s_p[2] + s_p[3]))
                    + ((s_p[4] + s_p[5]) + (s_p[6] + s_p[7]));
            g_batch[b] = x;
            g_bdone[b] = 0;                 // reset for next graph replay
            red_add_release(&g_done2, 1u);  // release g_batch[b], non-blocking
        }
        return;
    }

    // ---------------- Role 3: final scalar (fixed order) -------------------
    if (t == 0) {
        while (ld_acquire(&g_done2) < B_DIM)
            __nanosleep(128);
        float total = 0.0f;
#pragma unroll
        for (int i = 0; i < B_DIM; i++)
            total += __ldcg(g_batch + i);
        out[0] = total / ((float)HW * (float)(B_DIM * KTOP));
        g_done2 = 0;                        // reset for next graph replay
    }
}

extern "C" void kernel_launch(void* const* d_in, const int* in_sizes, int n_in,
                              void* d_out, int out_size)
{
    const float* inputs  = (const float*)d_in[0];
    const float* targets = (const float*)d_in[1];
    float* out = (float*)d_out;

    fused_kernel<<<GRID_TOTAL, 256>>>(inputs, targets, out);
}

// round 9
// speedup vs baseline: 1.1362x; 1.1362x over previous
#include <cuda_runtime.h>
#include <cuda_bf16.h>

// Problem shape (fixed by reference setup_inputs)
#define B_DIM 32
#define C_DIM 512
#define HW    4096            // 64*64
#define KTOP  256             // 0.5 * C
#define NBC   (B_DIM * C_DIM) // 16384
#define SEL_BLOCKS 128        // 32 batches x 4 channel groups

// Scratch (no cudaMalloc allowed; zero-initialized at module load)
__device__ float g_ssq[NBC];        // per-(b,c) sum of targets^2 (ranking key)
__device__ float g_ssd[NBC];        // per-(b,c) sum of (in - tgt)^2
__device__ float g_part[SEL_BLOCKS];
__device__ unsigned int g_done;     // self-resetting completion counter

// acq_rel atomicAdd: release = my prior stores (g_part) visible before the
// increment; acquire = if I observe count==SEL_BLOCKS-1, everyone else's
// g_part stores are visible to my subsequent loads. One op, no MEMBAR/IVALL.
__device__ __forceinline__ unsigned int atom_add_acq_rel(unsigned int* p, unsigned int v)
{
    unsigned int prev;
    asm volatile("atom.acq_rel.gpu.global.add.u32 %0, [%1], %2;"
                 : "=r"(prev) : "l"(p), "r"(v) : "memory");
    return prev;
}

// ---------------------------------------------------------------------------
// Kernel 1: streaming reduce. 512 threads per block, TWO (b,c) planes per
// block (warps 0-7 -> plane 2*bid, warps 8-15 -> plane 2*bid+1). Per-thread
// load pattern identical to the known-good wall kernel (8x LDG.128,
// streaming). Halves CTA dispatch/retire count vs the 256-thread version.
// Exit path stays pure (no atomics/fences — R4/R6/R8 lesson, n=3).
// ---------------------------------------------------------------------------
__global__ __launch_bounds__(512, 4) void bc_reduce_kernel(
    const float* __restrict__ inp,
    const float* __restrict__ tgt)
{
    const int bid = blockIdx.x;                 // 0 .. NBC/2-1
    const int t   = threadIdx.x;                // 0 .. 511
    const int half = t >> 8;                    // 0 or 1: which plane
    const int t256 = t & 255;

    const size_t plane = (size_t)(2 * bid + half);
    const float4* __restrict__ ip =
        reinterpret_cast<const float4*>(inp + plane * HW);
    const float4* __restrict__ tp =
        reinterpret_cast<const float4*>(tgt + plane * HW);

    float ssq = 0.0f;
    float ssd = 0.0f;

#pragma unroll
    for (int i = 0; i < 4; i++) {
        float4 a = __ldcs(ip + t256 + i * 256);
        float4 b = __ldcs(tp + t256 + i * 256);
        ssq = fmaf(b.x, b.x, ssq);
        ssq = fmaf(b.y, b.y, ssq);
        ssq = fmaf(b.z, b.z, ssq);
        ssq = fmaf(b.w, b.w, ssq);
        float dx = a.x - b.x;
        float dy = a.y - b.y;
        float dz = a.z - b.z;
        float dw = a.w - b.w;
        ssd = fmaf(dx, dx, ssd);
        ssd = fmaf(dy, dy, ssd);
        ssd = fmaf(dz, dz, ssd);
        ssd = fmaf(dw, dw, ssd);
    }

#pragma unroll
    for (int off = 16; off > 0; off >>= 1) {
        ssq += __shfl_xor_sync(0xFFFFFFFFu, ssq, off);
        ssd += __shfl_xor_sync(0xFFFFFFFFu, ssd, off);
    }

    __shared__ float s_ssq[16];
    __shared__ float s_ssd[16];
    const int warp = t >> 5;                    // 0..15 (0-7 plane0, 8-15 plane1)
    const int lane = t & 31;
    if (lane == 0) {
        s_ssq[warp] = ssq;
        s_ssd[warp] = ssd;
    }
    __syncthreads();

    if (warp == 0) {
        // lanes 0-7 reduce plane0's 8 partials, lanes 8-15 plane1's.
        float q = (lane < 16) ? s_ssq[lane] : 0.0f;
        float d = (lane < 16) ? s_ssd[lane] : 0.0f;
#pragma unroll
        for (int off = 4; off > 0; off >>= 1) {   // xor 4,2,1 stays within each 8-group
            q += __shfl_xor_sync(0xFFFFFFFFu, q, off);
            d += __shfl_xor_sync(0xFFFFFFFFu, d, off);
        }
        if (lane == 0) {
            g_ssq[2 * bid] = q;
            g_ssd[2 * bid] = d;
        }
        if (lane == 8) {
            g_ssq[2 * bid + 1] = q;
            g_ssd[2 * bid + 1] = d;
        }
    }

    __syncthreads();
    cudaTriggerProgrammaticLaunchCompletion();
}

// ---------------------------------------------------------------------------
// Kernel 2: fused select + final (PDL secondary). vs R7: the threadfence +
// plain atomicAdd pair is replaced by one acq_rel atomic; last block reads
// partials with __ldcg (ordered by the acquire). Deterministic fixed-order
// reductions; g_done self-resets for graph replay.
// ---------------------------------------------------------------------------
__global__ __launch_bounds__(128) void select_final_kernel(float* __restrict__ out)
{
    // PDL: wait until the upstream grid's memory (g_ssq/g_ssd) is visible.
    cudaGridDependencySynchronize();

    __shared__ float4 s_norm4[C_DIM / 4];   // 512 norms as 128 float4
    __shared__ float  s_p[4];
    __shared__ bool   s_last;

    const int b = blockIdx.x >> 2;     // batch
    const int g = blockIdx.x & 3;      // channel group (128 channels)
    const int t = threadIdx.x;
    const int warp = t >> 5;
    const int lane = t & 31;
    const int c = g * 128 + t;         // this thread's channel

    // Issue BOTH global loads up front: ssd's latency hides under the rank loop.
    const float my_ssd = g_ssd[b * C_DIM + c];
    s_norm4[t] = reinterpret_cast<const float4*>(g_ssq + b * C_DIM)[t];
    __syncthreads();

    const float v = reinterpret_cast<const float*>(s_norm4)[c];

    int cnt = 0;
#pragma unroll 4
    for (int j = 0; j < C_DIM / 4; j++) {
        float4 n = s_norm4[j];         // broadcast, conflict-free
        cnt += (n.x > v) ? 1 : 0;
        cnt += (n.y > v) ? 1 : 0;
        cnt += (n.z > v) ? 1 : 0;
        cnt += (n.w > v) ? 1 : 0;
    }

    float contrib = (cnt < KTOP) ? my_ssd : 0.0f;

#pragma unroll
    for (int off = 16; off > 0; off >>= 1)
        contrib += __shfl_xor_sync(0xFFFFFFFFu, contrib, off);
    if (lane == 0) s_p[warp] = contrib;
    __syncthreads();

    if (t == 0) {
        float x = (s_p[0] + s_p[1]) + (s_p[2] + s_p[3]);
        g_part[blockIdx.x] = x;
        // acq_rel: releases the g_part store, acquires everyone else's
        unsigned int prev = atom_add_acq_rel(&g_done, 1u);
        s_last = (prev == SEL_BLOCKS - 1);
    }
    __syncthreads();

    if (s_last) {
        float x = __ldcg(g_part + t);  // 128 partials; ordered by the acquire
#pragma unroll
        for (int off = 16; off > 0; off >>= 1)
            x += __shfl_xor_sync(0xFFFFFFFFu, x, off);

        __shared__ float s_f[4];
        if (lane == 0) s_f[warp] = x;
        __syncthreads();
        if (t == 0) {
            float total = (s_f[0] + s_f[1]) + (s_f[2] + s_f[3]);
            out[0] = total / ((float)HW * (float)(B_DIM * KTOP));
            g_done = 0;                // reset for next graph replay
        }
    }
}

extern "C" void kernel_launch(void* const* d_in, const int* in_sizes, int n_in,
                              void* d_out, int out_size)
{
    const float* inputs  = (const float*)d_in[0];
    const float* targets = (const float*)d_in[1];
    float* out = (float*)d_out;

    bc_reduce_kernel<<<NBC / 2, 512>>>(inputs, targets);

    // Dependent launch with programmatic stream serialization (PDL):
    // select_final_kernel's launch/prologue overlaps bc_reduce's tail.
    cudaLaunchConfig_t cfg = {};
    cfg.gridDim  = dim3(SEL_BLOCKS);
    cfg.blockDim = dim3(128);
    cfg.dynamicSmemBytes = 0;
    cfg.stream = 0;   // legacy default stream (same as <<<>>> above)
    cudaLaunchAttribute attrs[1];
    attrs[0].id = cudaLaunchAttributeProgrammaticStreamSerialization;
    attrs[0].val.programmaticStreamSerializationAllowed = 1;
    cfg.attrs = attrs;
    cfg.numAttrs = 1;
    cudaLaunchKernelEx(&cfg, select_final_kernel, out);
}

// round 10
// speedup vs baseline: 1.1688x; 1.0287x over previous
#include <cuda_runtime.h>
#include <cuda_bf16.h>

// Problem shape (fixed by reference setup_inputs)
#define B_DIM 32
#define C_DIM 512
#define HW    4096            // 64*64
#define KTOP  256             // 0.5 * C
#define NBC   (B_DIM * C_DIM) // 16384
#define SEL_BLOCKS 128        // 32 batches x 4 channel groups

// Fixed-point encoding for the single-atomic final reduction.
// Block partial <= ~1.3e6 (ssd ~8192 x 128 channels); x 2^18 ~= 3.4e11 << 2^57.
// Sum of 128 partials ~= 4.4e13 << 2^57. Count lives in bits [57,64).
#define FIXED_SCALE 262144.0f            // 2^18
#define COUNT_INC   (1ULL << 57)
#define SUM_MASK    (COUNT_INC - 1ULL)

// Scratch (no cudaMalloc allowed; zero-initialized at module load)
__device__ float g_ssq[NBC];            // per-(b,c) sum of targets^2 (ranking key)
__device__ float g_ssd[NBC];            // per-(b,c) sum of (in - tgt)^2
__device__ unsigned long long g_acc;    // packed {count:7, fixed-point sum:57}; self-reset

// ---------------------------------------------------------------------------
// Kernel 1: streaming reduce (UNCHANGED from the 82.7us config — at the HBM
// wall; exit path stays pure per the R4/R6/R8 n=3 lesson). 512 threads per
// block, two (b,c) planes per block, 8x LDG.128 streaming per thread.
// ---------------------------------------------------------------------------
__global__ __launch_bounds__(512, 4) void bc_reduce_kernel(
    const float* __restrict__ inp,
    const float* __restrict__ tgt)
{
    const int bid = blockIdx.x;                 // 0 .. NBC/2-1
    const int t   = threadIdx.x;                // 0 .. 511
    const int half = t >> 8;                    // which plane
    const int t256 = t & 255;

    const size_t plane = (size_t)(2 * bid + half);
    const float4* __restrict__ ip =
        reinterpret_cast<const float4*>(inp + plane * HW);
    const float4* __restrict__ tp =
        reinterpret_cast<const float4*>(tgt + plane * HW);

    float ssq = 0.0f;
    float ssd = 0.0f;

#pragma unroll
    for (int i = 0; i < 4; i++) {
        float4 a = __ldcs(ip + t256 + i * 256);
        float4 b = __ldcs(tp + t256 + i * 256);
        ssq = fmaf(b.x, b.x, ssq);
        ssq = fmaf(b.y, b.y, ssq);
        ssq = fmaf(b.z, b.z, ssq);
        ssq = fmaf(b.w, b.w, ssq);
        float dx = a.x - b.x;
        float dy = a.y - b.y;
        float dz = a.z - b.z;
        float dw = a.w - b.w;
        ssd = fmaf(dx, dx, ssd);
        ssd = fmaf(dy, dy, ssd);
        ssd = fmaf(dz, dz, ssd);
        ssd = fmaf(dw, dw, ssd);
    }

#pragma unroll
    for (int off = 16; off > 0; off >>= 1) {
        ssq += __shfl_xor_sync(0xFFFFFFFFu, ssq, off);
        ssd += __shfl_xor_sync(0xFFFFFFFFu, ssd, off);
    }

    __shared__ float s_ssq[16];
    __shared__ float s_ssd[16];
    const int warp = t >> 5;                    // 0..15 (0-7 plane0, 8-15 plane1)
    const int lane = t & 31;
    if (lane == 0) {
        s_ssq[warp] = ssq;
        s_ssd[warp] = ssd;
    }
    __syncthreads();

    if (warp == 0) {
        float q = (lane < 16) ? s_ssq[lane] : 0.0f;
        float d = (lane < 16) ? s_ssd[lane] : 0.0f;
#pragma unroll
        for (int off = 4; off > 0; off >>= 1) {   // xor 4,2,1 stays within each 8-group
            q += __shfl_xor_sync(0xFFFFFFFFu, q, off);
            d += __shfl_xor_sync(0xFFFFFFFFu, d, off);
        }
        if (lane == 0) {
            g_ssq[2 * bid] = q;
            g_ssd[2 * bid] = d;
        }
        if (lane == 8) {
            g_ssq[2 * bid + 1] = q;
            g_ssd[2 * bid + 1] = d;
        }
    }

    __syncthreads();
    cudaTriggerProgrammaticLaunchCompletion();
}

// ---------------------------------------------------------------------------
// Kernel 2: select + final (PDL secondary). 128 blocks x 256 threads.
// Each block: one (batch, 128-channel group). The 512-way rank count per
// channel is SPLIT across two threads (64 float4 iters each), combined via
// SMEM. Block partial is converted to fixed-point and folded into ONE packed
// u64 atomicAdd (sum in low 57 bits, arrival count in top 7). The 128th
// arrival computes the exact integer total, writes the scalar, resets g_acc.
// Integer adds commute -> bitwise deterministic for any arrival order.
// ---------------------------------------------------------------------------
__global__ __launch_bounds__(256) void select_final_kernel(float* __restrict__ out)
{
    // PDL: wait until the upstream grid's memory (g_ssq/g_ssd) is visible.
    cudaGridDependencySynchronize();

    __shared__ float4 s_norm4[C_DIM / 4];   // all 512 norms of this batch
    __shared__ int    s_cnt[128];           // half-1 partial counts
    __shared__ float  s_p[8];

    const int b  = blockIdx.x >> 2;    // batch
    const int g  = blockIdx.x & 3;     // channel group (128 channels)
    const int t  = threadIdx.x;        // 0..255
    const int cl = t & 127;            // channel-within-group
    const int hf = t >> 7;             // which half of the 512 to scan
    const int warp = t >> 5;
    const int lane = t & 31;
    const int c = g * 128 + cl;        // this thread's channel

    // Hoist global loads: latency hides under the rank loop.
    const float my_ssd = (hf == 0) ? g_ssd[b * C_DIM + c] : 0.0f;
    if (t < C_DIM / 4)
        s_norm4[t] = reinterpret_cast<const float4*>(g_ssq + b * C_DIM)[t];
    __syncthreads();

    const float v = reinterpret_cast<const float*>(s_norm4)[c];

    // Each thread scans 64 float4 (256 norms): half 0 -> j in [0,64),
    // half 1 -> j in [64,128).
    int cnt = 0;
    const int j0 = hf * 64;
#pragma unroll 4
    for (int j = j0; j < j0 + 64; j++) {
        float4 n = s_norm4[j];         // broadcast, conflict-free
        cnt += (n.x > v) ? 1 : 0;
        cnt += (n.y > v) ? 1 : 0;
        cnt += (n.z > v) ? 1 : 0;
        cnt += (n.w > v) ? 1 : 0;
    }

    if (hf == 1) s_cnt[cl] = cnt;
    __syncthreads();

    float contrib = 0.0f;
    if (hf == 0) {
        const int total_cnt = cnt + s_cnt[cl];
        contrib = (total_cnt < KTOP) ? my_ssd : 0.0f;
    }

#pragma unroll
    for (int off = 16; off > 0; off >>= 1)
        contrib += __shfl_xor_sync(0xFFFFFFFFu, contrib, off);
    if (lane == 0) s_p[warp] = contrib;
    __syncthreads();

    if (t == 0) {
        const float part = ((s_p[0] + s_p[1]) + (s_p[2] + s_p[3]))
                         + ((s_p[4] + s_p[5]) + (s_p[6] + s_p[7]));
        // Fixed-point fold + arrival count, in ONE relaxed atomic.
        const unsigned long long mine =
            (unsigned long long)(part * FIXED_SCALE) + COUNT_INC;
        const unsigned long long prev = atomicAdd(&g_acc, mine);
        if ((prev >> 57) == (unsigned long long)(SEL_BLOCKS - 1)) {
            // I'm the 128th arrival: exact integer total is prev's sum + mine.
            const unsigned long long tot = (prev & SUM_MASK) + (mine & SUM_MASK);
            out[0] = ((float)tot / FIXED_SCALE)
                   / ((float)HW * (float)(B_DIM * KTOP));
            g_acc = 0ULL;              // reset for next graph replay
        }
    }
}

extern "C" void kernel_launch(void* const* d_in, const int* in_sizes, int n_in,
                              void* d_out, int out_size)
{
    const float* inputs  = (const float*)d_in[0];
    const float* targets = (const float*)d_in[1];
    float* out = (float*)d_out;

    bc_reduce_kernel<<<NBC / 2, 512>>>(inputs, targets);

    // Dependent launch with programmatic stream serialization (PDL):
    // select_final_kernel's launch/prologue overlaps bc_reduce's tail.
    cudaLaunchConfig_t cfg = {};
    cfg.gridDim  = dim3(SEL_BLOCKS);
    cfg.blockDim = dim3(256);
    cfg.dynamicSmemBytes = 0;
    cfg.stream = 0;   // legacy default stream (same as <<<>>> above)
    cudaLaunchAttribute attrs[1];
    attrs[0].id = cudaLaunchAttributeProgrammaticStreamSerialization;
    attrs[0].val.programmaticStreamSerializationAllowed = 1;
    cfg.attrs = attrs;
    cfg.numAttrs = 1;
    cudaLaunchKernelEx(&cfg, select_final_kernel, out);
}